// round 6
// baseline (speedup 1.0000x reference)
#include <cuda_runtime.h>
#include <cstdint>

#define NGS 10

constexpr int IN_COLS   = 4 * NGS;        // 40
constexpr int OUT_COLS  = 6 * NGS;        // 60
constexpr int IN_STRIDE = 44;             // mult of 4 (16B rows), conflict-free LDS.128
constexpr int WARPS     = 4;
constexpr int THREADS   = WARPS * 32;     // 128
constexpr int BUF_FLOATS  = 32 * OUT_COLS;            // 1920: overlaid in(1408)/out(1920)
constexpr int SMEM_BYTES  = WARPS * BUF_FLOATS * 4;   // 30720 -> 7 blocks/SM
constexpr int BLOCKS_PER_SM = 7;

__device__ __forceinline__ void cp_async16(float* smem_dst, const void* gsrc) {
    uint32_t s = (uint32_t)__cvta_generic_to_shared(smem_dst);
    asm volatile("cp.async.cg.shared.global [%0], [%1], 16;"
                 :: "r"(s), "l"(gsrc) : "memory");
}

__global__ __launch_bounds__(THREADS, BLOCKS_PER_SM)
void kmap_kernel(const float* __restrict__ var,
                 const float* __restrict__ slider_lengths,
                 const float* __restrict__ scos_g,
                 const float* __restrict__ ssin_g,
                 const float* __restrict__ note_dist,
                 const float* __restrict__ tick_diff,
                 const float* __restrict__ start_pos,
                 const int*   __restrict__ is_slider,
                 float* __restrict__ out,
                 int B, int cpw)
{
    extern __shared__ float smem[];
    __shared__ float s_wl[NGS], s_wr[NGS], s_wt[NGS], s_wb[NGS], s_l[NGS],
                     s_rr[NGS], s_sln[NGS], s_scos[NGS], s_ssin[NGS];
    __shared__ int   s_isl[NGS];
    __shared__ float s_p0[2];

    const int tid  = threadIdx.x;
    const int wid  = tid >> 5;
    const int lane = tid & 31;

    float* sBuf = smem + wid * BUF_FLOATS;

    const int NT    = (B + 31) >> 5;                 // 32-row tiles
    const int gw    = blockIdx.x * WARPS + wid;      // global warp id
    int tStart = gw * cpw;                           // contiguous chunk per warp
    int tEnd   = tStart + cpw;
    if (tEnd > NT) tEnd = NT;

    // ---- prefetch tile t's input into the overlay buffer ----
    auto prefetch = [&](int t) {
        if ((B - t * 32) >= 32) {
            const float4* gin = reinterpret_cast<const float4*>(var + (size_t)t * 32 * IN_COLS);
            #pragma unroll
            for (int it = 0; it < (32 * IN_COLS) / 128; ++it) {   // 10 x 16B/thread
                int j4 = it * 32 + lane;
                int e = j4 * 4;
                int r = e / IN_COLS;
                cp_async16(sBuf + e + 4 * r, &gin[j4]);   // padded: r*44 + c
            }
            asm volatile("cp.async.commit_group;" ::: "memory");
        }
    };

    if (tStart < tEnd) prefetch(tStart);   // first tile in flight before param init

    if (tid < NGS) {
        float l   = note_dist[tid];           // LMUL = 1.0
        s_l[tid]  = l;
        s_wl[tid] = 0.05f * 512.0f + 0.5f * l;
        s_wr[tid] = 0.95f * 512.0f - 0.5f * l;
        s_wt[tid] = 0.05f * 384.0f + 0.5f * l;
        s_wb[tid] = 0.95f * 384.0f - 0.5f * l;
        s_rr[tid] = (tick_diff[tid] <= 1.0f) ? 0.0f : 1.0f;  // rerand
        s_sln[tid]  = slider_lengths[tid];
        s_scos[tid] = scos_g[tid];
        s_ssin[tid] = ssin_g[tid];
        s_isl[tid]  = is_slider[tid];
    }
    if (tid == 0) { s_p0[0] = start_pos[0]; s_p0[1] = start_pos[1]; }
    __syncthreads();   // the only block-wide sync

    for (int t = tStart; t < tEnd; ++t) {
        int rows = B - t * 32; if (rows > 32) rows = 32;

        if (rows == 32) {
            asm volatile("cp.async.wait_group 0;" ::: "memory");
            __syncwarp();

            // ---- stage inputs to registers (10 x LDS.128, conflict-free) ----
            float rin[IN_COLS];
            const float* rowp = sBuf + lane * IN_STRIDE;
            #pragma unroll
            for (int c = 0; c < IN_COLS / 4; ++c) {
                float4 v = *reinterpret_cast<const float4*>(rowp + 4 * c);
                rin[4*c+0] = v.x; rin[4*c+1] = v.y; rin[4*c+2] = v.z; rin[4*c+3] = v.w;
            }
            __syncwarp();   // all lanes staged before STS overwrites the overlay

            // ---- compute: serial scan; k-pairs emitted as 3x STS.128 ----
            float* orow = sBuf + lane * OUT_COLS;   // raw stride 60, 16B-aligned rows
            float px = s_p0[0], py = s_p0[1];
            #pragma unroll
            for (int kp = 0; kp < NGS / 2; ++kp) {
                float o[12];
                #pragma unroll
                for (int h = 0; h < 2; ++h) {
                    const int k = 2 * kp + h;
                    float vk   = rin[k];
                    float vkh  = rin[NGS + k];
                    float v2k  = rin[2 * NGS + k];
                    float v2kh = rin[3 * NGS + k];

                    float inv  = rsqrtf(vk * vk + v2k * v2k);
                    float ck   = vk  * inv,  sk  = v2k  * inv;
                    float invh = rsqrtf(vkh * vkh + v2kh * v2kh);
                    float ckh  = vkh * invh, skh = v2kh * invh;

                    float rr = s_rr[k], nr = 1.0f - rr;
                    float lk = s_l[k];
                    float dx = lk * ck, dy = lk * sk;
                    float wl = s_wl[k], wr = s_wr[k], wt = s_wt[k], wb = s_wb[k];

                    float xd = (px < wl) ?  fabsf(dx)
                             : (px > wr) ? -fabsf(dx)
                             : ((px > wl) && (px < wr)) ? dx : 0.0f;
                    float yd = (py < wt) ?  fabsf(dy)
                             : (py > wb) ? -fabsf(dy)
                             : ((py > wt) && (py < wb)) ? dy : 0.0f;

                    float x = rr * (256.0f + 256.0f * vk)  + nr * (px + xd);
                    float y = rr * (192.0f + 192.0f * v2k) + nr * (py + yd);

                    float c0 = x * (1.0f / 512.0f);
                    float c1 = y * (1.0f / 384.0f);
                    float c2, c3, c4, c5;
                    if (s_isl[k]) {   // uniform per k
                        c2 = ckh * s_scos[k] - skh * s_ssin[k];
                        c3 = ckh * s_ssin[k] + skh * s_scos[k];
                        c4 = (x + ckh * s_sln[k]) * (1.0f / 512.0f);
                        c5 = (y + skh * s_sln[k]) * (1.0f / 384.0f);
                    } else {
                        c2 = rr * ckh + nr * ck;
                        c3 = rr * skh + nr * sk;
                        c4 = c0; c5 = c1;
                    }
                    o[6*h+0] = c0; o[6*h+1] = c1; o[6*h+2] = c2;
                    o[6*h+3] = c3; o[6*h+4] = c4; o[6*h+5] = c5;
                    px = x; py = y;   // NFSE == False
                }
                float4* dst = reinterpret_cast<float4*>(orow + 12 * kp);
                dst[0] = make_float4(o[0], o[1], o[2],  o[3]);
                dst[1] = make_float4(o[4], o[5], o[6],  o[7]);
                dst[2] = make_float4(o[8], o[9], o[10], o[11]);
            }

            // ---- TMA bulk store (contiguous 7680B), drain, then prefetch next ----
            asm volatile("fence.proxy.async.shared::cta;" ::: "memory");
            __syncwarp();
            if (lane == 0) {
                uint32_t s = (uint32_t)__cvta_generic_to_shared(sBuf);
                float* g = out + (size_t)t * 32 * OUT_COLS;
                asm volatile("cp.async.bulk.global.shared::cta.bulk_group [%0], [%1], %2;"
                             :: "l"(g), "r"(s), "n"(32 * OUT_COLS * 4) : "memory");
                asm volatile("cp.async.bulk.commit_group;" ::: "memory");
                asm volatile("cp.async.bulk.wait_group 0;" ::: "memory");  // buffer reusable
            }
            __syncwarp();
            if (t + 1 < tEnd) prefetch(t + 1);
        } else if (lane < rows) {
            // ---- partial tile fallback: direct scalar global path ----
            const float* grow  = var + (size_t)(t * 32 + lane) * IN_COLS;
            float*       gorow = out + (size_t)(t * 32 + lane) * OUT_COLS;
            float px = s_p0[0], py = s_p0[1];
            #pragma unroll
            for (int k = 0; k < NGS; ++k) {
                float vk   = grow[k];
                float vkh  = grow[NGS + k];
                float v2k  = grow[2 * NGS + k];
                float v2kh = grow[3 * NGS + k];
                float inv  = rsqrtf(vk * vk + v2k * v2k);
                float ck   = vk  * inv,  sk  = v2k  * inv;
                float invh = rsqrtf(vkh * vkh + v2kh * v2kh);
                float ckh  = vkh * invh, skh = v2kh * invh;
                float rr = s_rr[k], nr = 1.0f - rr;
                float lk = s_l[k];
                float dx = lk * ck, dy = lk * sk;
                float xd = (px < s_wl[k]) ?  fabsf(dx)
                         : (px > s_wr[k]) ? -fabsf(dx)
                         : ((px > s_wl[k]) && (px < s_wr[k])) ? dx : 0.0f;
                float yd = (py < s_wt[k]) ?  fabsf(dy)
                         : (py > s_wb[k]) ? -fabsf(dy)
                         : ((py > s_wt[k]) && (py < s_wb[k])) ? dy : 0.0f;
                float x = rr * (256.0f + 256.0f * vk)  + nr * (px + xd);
                float y = rr * (192.0f + 192.0f * v2k) + nr * (py + yd);
                float c0 = x * (1.0f / 512.0f), c1 = y * (1.0f / 384.0f);
                float c2, c3, c4, c5;
                if (s_isl[k]) {
                    c2 = ckh * s_scos[k] - skh * s_ssin[k];
                    c3 = ckh * s_ssin[k] + skh * s_scos[k];
                    c4 = (x + ckh * s_sln[k]) * (1.0f / 512.0f);
                    c5 = (y + skh * s_sln[k]) * (1.0f / 384.0f);
                } else {
                    c2 = rr * ckh + nr * ck; c3 = rr * skh + nr * sk;
                    c4 = c0; c5 = c1;
                }
                gorow[6*k+0] = c0; gorow[6*k+1] = c1; gorow[6*k+2] = c2;
                gorow[6*k+3] = c3; gorow[6*k+4] = c4; gorow[6*k+5] = c5;
                px = x; py = y;
            }
        }
    }
}

extern "C" void kernel_launch(void* const* d_in, const int* in_sizes, int n_in,
                              void* d_out, int out_size)
{
    const float* var  = (const float*)d_in[0];
    const float* sln  = (const float*)d_in[1];
    const float* scos = (const float*)d_in[2];
    const float* ssin = (const float*)d_in[3];
    const float* nd   = (const float*)d_in[4];
    const float* td   = (const float*)d_in[5];
    const float* sp   = (const float*)d_in[6];
    const int*   isl  = (const int*)d_in[7];
    float* out = (float*)d_out;

    int B  = in_sizes[0] / IN_COLS;
    int NT = (B + 31) >> 5;

    int nsm = 148;
    cudaDeviceGetAttribute(&nsm, cudaDevAttrMultiProcessorCount, 0);

    int blocks = nsm * BLOCKS_PER_SM;                 // persistent single wave
    int maxBlocks = (NT + WARPS - 1) / WARPS;
    if (blocks > maxBlocks) blocks = maxBlocks;
    if (blocks < 1) blocks = 1;

    int gridWarps = blocks * WARPS;
    int cpw = (NT + gridWarps - 1) / gridWarps;       // contiguous tiles per warp

    cudaFuncSetAttribute(kmap_kernel,
                         cudaFuncAttributeMaxDynamicSharedMemorySize, SMEM_BYTES);
    kmap_kernel<<<blocks, THREADS, SMEM_BYTES>>>(var, sln, scos, ssin, nd, td,
                                                 sp, isl, out, B, cpw);
}

// round 7
// speedup vs baseline: 1.2113x; 1.2113x over previous
#include <cuda_runtime.h>
#include <cstdint>

#define NGS 10

constexpr int IN_COLS   = 4 * NGS;        // 40
constexpr int OUT_COLS  = 6 * NGS;        // 60
constexpr int IN_STRIDE = 44;             // mult of 4 (16B rows), conflict-free LDS.128
constexpr int WARPS     = 2;
constexpr int THREADS   = WARPS * 32;     // 64
constexpr int ROWS_PER_BLOCK = THREADS;   // 1 row per thread
constexpr int BUF_FLOATS  = 32 * OUT_COLS;            // 1920: overlaid in(1408)/out(1920)
constexpr int SMEM_BYTES  = WARPS * BUF_FLOATS * 4;   // 15360 -> 14 blocks/SM
constexpr int BLOCKS_PER_SM = 14;

__device__ __forceinline__ void cp_async16(float* smem_dst, const void* gsrc) {
    uint32_t s = (uint32_t)__cvta_generic_to_shared(smem_dst);
    asm volatile("cp.async.cg.shared.global [%0], [%1], 16;"
                 :: "r"(s), "l"(gsrc) : "memory");
}

__global__ __launch_bounds__(THREADS, BLOCKS_PER_SM)
void kmap_kernel(const float* __restrict__ var,
                 const float* __restrict__ slider_lengths,
                 const float* __restrict__ scos_g,
                 const float* __restrict__ ssin_g,
                 const float* __restrict__ note_dist,
                 const float* __restrict__ tick_diff,
                 const float* __restrict__ start_pos,
                 const int*   __restrict__ is_slider,
                 float* __restrict__ out,
                 int B)
{
    extern __shared__ float smem[];
    __shared__ float s_wl[NGS], s_wr[NGS], s_wt[NGS], s_wb[NGS], s_l[NGS],
                     s_rr[NGS], s_sln[NGS], s_scos[NGS], s_ssin[NGS];
    __shared__ int   s_isl[NGS];
    __shared__ float s_p0[2];

    const int tid  = threadIdx.x;
    const int wid  = tid >> 5;
    const int lane = tid & 31;

    float* sBuf = smem + wid * BUF_FLOATS;
    const int warpRow = blockIdx.x * ROWS_PER_BLOCK + wid * 32;
    const int rows = (B - warpRow) < 32 ? (B - warpRow) : 32;

    // ---- Kick off async input copy FIRST (overlap latency with param init) ----
    if (rows == 32) {
        const float4* gin = reinterpret_cast<const float4*>(var + (size_t)warpRow * IN_COLS);
        #pragma unroll
        for (int it = 0; it < (32 * IN_COLS) / 128; ++it) {   // 10 x 16B per thread
            int j4 = it * 32 + lane;
            int e = j4 * 4;
            int r = e / IN_COLS;
            cp_async16(sBuf + e + 4 * r, &gin[j4]);   // padded: r*44 + c
        }
        asm volatile("cp.async.commit_group;" ::: "memory");
    } else if (rows > 0) {
        for (int j = lane; j < rows * IN_COLS; j += 32) {
            int r = j / IN_COLS, c = j - r * IN_COLS;
            sBuf[r * IN_STRIDE + c] = var[(size_t)warpRow * IN_COLS + j];
        }
    }

    // ---- Per-group scalar params (uniform across batch) ----
    if (tid < NGS) {
        float l   = note_dist[tid];           // LMUL = 1.0
        s_l[tid]  = l;
        s_wl[tid] = 0.05f * 512.0f + 0.5f * l;
        s_wr[tid] = 0.95f * 512.0f - 0.5f * l;
        s_wt[tid] = 0.05f * 384.0f + 0.5f * l;
        s_wb[tid] = 0.95f * 384.0f - 0.5f * l;
        s_rr[tid] = (tick_diff[tid] <= 1.0f) ? 0.0f : 1.0f;  // rerand
        s_sln[tid]  = slider_lengths[tid];
        s_scos[tid] = scos_g[tid];
        s_ssin[tid] = ssin_g[tid];
        s_isl[tid]  = is_slider[tid];
    }
    if (tid == 0) { s_p0[0] = start_pos[0]; s_p0[1] = start_pos[1]; }
    __syncthreads();   // params visible; the only block-wide sync

    if (rows == 32) {
        asm volatile("cp.async.wait_group 0;" ::: "memory");
    }
    __syncwarp();

    // ---- Stage inputs to registers (10 x LDS.128, conflict-free), then overlay ----
    float rin[IN_COLS];
    if (lane < rows) {
        const float* row = sBuf + lane * IN_STRIDE;
        #pragma unroll
        for (int c = 0; c < IN_COLS / 4; ++c) {
            float4 t = *reinterpret_cast<const float4*>(row + 4 * c);
            rin[4*c+0] = t.x; rin[4*c+1] = t.y; rin[4*c+2] = t.z; rin[4*c+3] = t.w;
        }
    }
    __syncwarp();   // all inputs in regs before output overwrites the buffer

    // ---- Compute: serial scan; k-pairs emitted as 3x STS.128 into RAW layout ----
    if (lane < rows) {
        float* orow = sBuf + lane * OUT_COLS;   // raw stride 60, 16B-aligned rows
        float px = s_p0[0], py = s_p0[1];
        #pragma unroll
        for (int kp = 0; kp < NGS / 2; ++kp) {
            float o[12];
            #pragma unroll
            for (int h = 0; h < 2; ++h) {
                const int k = 2 * kp + h;
                float vk   = rin[k];
                float vkh  = rin[NGS + k];
                float v2k  = rin[2 * NGS + k];
                float v2kh = rin[3 * NGS + k];

                float inv  = rsqrtf(vk * vk + v2k * v2k);
                float ck   = vk  * inv,  sk  = v2k  * inv;
                float invh = rsqrtf(vkh * vkh + v2kh * v2kh);
                float ckh  = vkh * invh, skh = v2kh * invh;

                float rr = s_rr[k], nr = 1.0f - rr;
                float lk = s_l[k];
                float dx = lk * ck, dy = lk * sk;
                float wl = s_wl[k], wr = s_wr[k], wt = s_wt[k], wb = s_wb[k];

                float xd = (px < wl) ?  fabsf(dx)
                         : (px > wr) ? -fabsf(dx)
                         : ((px > wl) && (px < wr)) ? dx : 0.0f;
                float yd = (py < wt) ?  fabsf(dy)
                         : (py > wb) ? -fabsf(dy)
                         : ((py > wt) && (py < wb)) ? dy : 0.0f;

                float x = rr * (256.0f + 256.0f * vk)  + nr * (px + xd);
                float y = rr * (192.0f + 192.0f * v2k) + nr * (py + yd);

                float c0 = x * (1.0f / 512.0f);
                float c1 = y * (1.0f / 384.0f);
                float c2, c3, c4, c5;
                if (s_isl[k]) {   // uniform per k
                    c2 = ckh * s_scos[k] - skh * s_ssin[k];
                    c3 = ckh * s_ssin[k] + skh * s_scos[k];
                    c4 = (x + ckh * s_sln[k]) * (1.0f / 512.0f);
                    c5 = (y + skh * s_sln[k]) * (1.0f / 384.0f);
                } else {
                    c2 = rr * ckh + nr * ck;
                    c3 = rr * skh + nr * sk;
                    c4 = c0; c5 = c1;
                }
                o[6*h+0] = c0; o[6*h+1] = c1; o[6*h+2] = c2;
                o[6*h+3] = c3; o[6*h+4] = c4; o[6*h+5] = c5;
                px = x; py = y;   // NFSE == False
            }
            float4* dst = reinterpret_cast<float4*>(orow + 12 * kp);  // 48B-aligned
            dst[0] = make_float4(o[0], o[1], o[2],  o[3]);
            dst[1] = make_float4(o[4], o[5], o[6],  o[7]);
            dst[2] = make_float4(o[8], o[9], o[10], o[11]);
        }
    }
    __syncwarp();

    // ---- Store phase: single TMA bulk copy, smem (raw layout) -> global ----
    if (rows == 32) {
        asm volatile("fence.proxy.async.shared::cta;" ::: "memory");
        __syncwarp();
        if (lane == 0) {
            uint32_t s = (uint32_t)__cvta_generic_to_shared(sBuf);
            float* g = out + (size_t)warpRow * OUT_COLS;   // contiguous 7680B
            asm volatile("cp.async.bulk.global.shared::cta.bulk_group [%0], [%1], %2;"
                         :: "l"(g), "r"(s), "n"(32 * OUT_COLS * 4) : "memory");
            asm volatile("cp.async.bulk.commit_group;" ::: "memory");
            asm volatile("cp.async.bulk.wait_group 0;" ::: "memory");
        }
    } else if (rows > 0) {
        for (int j = lane; j < rows * OUT_COLS; j += 32) {
            int r = j / OUT_COLS, c = j - r * OUT_COLS;
            out[(size_t)warpRow * OUT_COLS + j] = sBuf[r * OUT_COLS + c];
        }
    }
}

extern "C" void kernel_launch(void* const* d_in, const int* in_sizes, int n_in,
                              void* d_out, int out_size)
{
    const float* var  = (const float*)d_in[0];
    const float* sln  = (const float*)d_in[1];
    const float* scos = (const float*)d_in[2];
    const float* ssin = (const float*)d_in[3];
    const float* nd   = (const float*)d_in[4];
    const float* td   = (const float*)d_in[5];
    const float* sp   = (const float*)d_in[6];
    const int*   isl  = (const int*)d_in[7];
    float* out = (float*)d_out;

    int B = in_sizes[0] / IN_COLS;

    cudaFuncSetAttribute(kmap_kernel,
                         cudaFuncAttributeMaxDynamicSharedMemorySize, SMEM_BYTES);
    int blocks = (B + ROWS_PER_BLOCK - 1) / ROWS_PER_BLOCK;
    kmap_kernel<<<blocks, THREADS, SMEM_BYTES>>>(var, sln, scos, ssin, nd, td,
                                                 sp, isl, out, B);
}